// round 12
// baseline (speedup 1.0000x reference)
#include <cuda_runtime.h>
#include <cuda_bf16.h>
#include <math.h>
#include <stdint.h>

#define N_  16
#define C_  128
#define S_  16384
#define K_  64
#define TS  64
#define TILES 16
#define SGROUPS (S_ / (TS * TILES))   // 16
#define NBLK (N_ * SGROUPS)           // 256
#define NTH 256
#define LDX 136   // bf16 row stride x tiles [s][c] (col 128 = ||x|| hi/lo)
#define LDW 136
#define LDK 72    // bf16 row stride soft [s][k]
#define PSTRIDE 8256                  // 8192 vacc + 64 asum per block partial

__device__ float g_part[NBLK * PSTRIDE];
__device__ float g_red[N_ * PSTRIDE];

// ---------------------------------------------------------------------------
__device__ __forceinline__ uint32_t s2u(const void* p) {
    uint32_t a;
    asm("{ .reg .u64 t; cvta.to.shared.u64 t, %1; cvt.u32.u64 %0, t; }"
        : "=r"(a) : "l"(p));
    return a;
}
__device__ __forceinline__ void ldsm4(uint32_t* r, uint32_t addr) {
    asm volatile("ldmatrix.sync.aligned.m8n8.x4.shared.b16 {%0,%1,%2,%3}, [%4];"
                 : "=r"(r[0]), "=r"(r[1]), "=r"(r[2]), "=r"(r[3]) : "r"(addr));
}
__device__ __forceinline__ void ldsm4t(uint32_t* r, uint32_t addr) {
    asm volatile("ldmatrix.sync.aligned.m8n8.x4.trans.shared.b16 {%0,%1,%2,%3}, [%4];"
                 : "=r"(r[0]), "=r"(r[1]), "=r"(r[2]), "=r"(r[3]) : "r"(addr));
}
__device__ __forceinline__ void ldsm2t(uint32_t& r0, uint32_t& r1, uint32_t addr) {
    asm volatile("ldmatrix.sync.aligned.m8n8.x2.trans.shared.b16 {%0,%1}, [%2];"
                 : "=r"(r0), "=r"(r1) : "r"(addr));
}
__device__ __forceinline__ void mma_bf16(float* d, const uint32_t* a,
                                         uint32_t b0, uint32_t b1) {
    asm volatile("mma.sync.aligned.m16n8k16.row.col.f32.bf16.bf16.f32 "
                 "{%0,%1,%2,%3}, {%4,%5,%6,%7}, {%8,%9}, {%0,%1,%2,%3};"
                 : "+f"(d[0]), "+f"(d[1]), "+f"(d[2]), "+f"(d[3])
                 : "r"(a[0]), "r"(a[1]), "r"(a[2]), "r"(a[3]), "r"(b0), "r"(b1));
}
__device__ __forceinline__ uint32_t bf2_pack(float lo, float hi) {
    __nv_bfloat162 p;
    p.x = __float2bfloat16(lo); p.y = __float2bfloat16(hi);
    return *(uint32_t*)&p;
}

// ---------------------------------------------------------------------------
// smem byte offsets (ldsm bases 128-aligned)
#define OFF_XH   0
#define OFF_XL   17408
#define OFF_WH   34816
#define OFF_WL   52224
#define OFF_SH   69632        // soft hi [s][k] 64 x 72 bf16
#define OFF_SL   78848        // soft lo
#define OFF_BB   88064
#define OFF_PN   88320        // float[64][4]
#define OFF_PS   89344        // float[64][2]
#define SMEM_TOT 89856

__global__ __launch_bounds__(NTH, 2)
void nv_main_kernel(const float* __restrict__ x,
                    const float* __restrict__ fc_w,
                    const float* __restrict__ fc_b) {
    extern __shared__ char smem[];
    __nv_bfloat16* XH  = (__nv_bfloat16*)(smem + OFF_XH);
    __nv_bfloat16* XL  = (__nv_bfloat16*)(smem + OFF_XL);
    __nv_bfloat16* WH  = (__nv_bfloat16*)(smem + OFF_WH);
    __nv_bfloat16* WL  = (__nv_bfloat16*)(smem + OFF_WL);
    __nv_bfloat16* SHm = (__nv_bfloat16*)(smem + OFF_SH);
    __nv_bfloat16* SLm = (__nv_bfloat16*)(smem + OFF_SL);
    float* BB = (float*)(smem + OFF_BB);
    float* PN = (float*)(smem + OFF_PN);
    float* PS = (float*)(smem + OFF_PS);

    const uint32_t XHu = s2u(XH), XLu = s2u(XL), WHu = s2u(WH), WLu = s2u(WL);
    const uint32_t SHu = s2u(SHm), SLu = s2u(SLm);

    const int n   = blockIdx.x >> 4;
    const int g   = blockIdx.x & (SGROUPS - 1);
    const int tid = threadIdx.x;
    const int l   = tid & 31;
    const int w   = tid >> 5;            // 0..7
    const int sl  = tid & 63;            // position (load/convert)
    const int q   = tid >> 6;            // channel quarter 0..3

    // GEMM1 split: m-stripe (w&3) over s, K-half kh (w>>2)
    const int m0g1 = (w & 3) * 16;
    const int kh   = w >> 2;
    // GEMM2 split: k-half (w&1)*32, c-quarter (w>>1)*32
    const int m0b  = (w & 1) * 32;
    const int nb   = (w >> 1) * 32;

    // ---- load fc_w hi/lo + bias (once per block) ----
    for (int i = tid; i < K_ * C_; i += NTH) {
        int k = i >> 7, c = i & 127;
        float v = fc_w[i];
        __nv_bfloat16 hi = __float2bfloat16(v);
        WH[k * LDW + c] = hi;
        WL[k * LDW + c] = __float2bfloat16(v - __bfloat162float(hi));
    }
    if (tid < K_) BB[tid] = fc_b[tid];
    __syncthreads();

    const int cst = (l & 3) * 2;
    float bias_r[4][2];
    #pragma unroll
    for (int j = 0; j < 4; j++) {
        bias_r[j][0] = BB[kh * 32 + j * 8 + cst];
        bias_r[j][1] = BB[kh * 32 + j * 8 + cst + 1];
    }

    float vacc[2][4][4];
    #pragma unroll
    for (int mi = 0; mi < 2; mi++)
        #pragma unroll
        for (int j = 0; j < 4; j++)
            #pragma unroll
            for (int p = 0; p < 4; p++) vacc[mi][j][p] = 0.0f;
    float vacc8[2][4];
    #pragma unroll
    for (int mi = 0; mi < 2; mi++)
        #pragma unroll
        for (int p = 0; p < 4; p++) vacc8[mi][p] = 0.0f;

    #pragma unroll 1
    for (int t = 0; t < TILES; t++) {
        const int s0 = g * (TS * TILES) + t * TS;
        const float* xg = x + (size_t)n * C_ * S_ + s0;
        __syncthreads();                         // A: prev tile consumers done

        // ---- convert: 16B-chunk stores (conflict-free STS.128) ----
        float ss = 0.0f;
        #pragma unroll
        for (int ch = 0; ch < 4; ch++) {
            const int c0 = q * 32 + ch * 8;
            uint32_t hp[4], lp[4];
            #pragma unroll
            for (int u = 0; u < 4; u++) {
                float v0 = xg[(size_t)(c0 + 2*u)     * S_ + sl];
                float v1 = xg[(size_t)(c0 + 2*u + 1) * S_ + sl];
                ss = fmaf(v0, v0, ss); ss = fmaf(v1, v1, ss);
                __nv_bfloat16 h0 = __float2bfloat16(v0);
                __nv_bfloat16 h1 = __float2bfloat16(v1);
                __nv_bfloat162 hv; hv.x = h0; hv.y = h1;
                hp[u] = *(uint32_t*)&hv;
                lp[u] = bf2_pack(v0 - __bfloat162float(h0),
                                 v1 - __bfloat162float(h1));
            }
            *(uint4*)&XH[sl * LDX + c0] = make_uint4(hp[0], hp[1], hp[2], hp[3]);
            *(uint4*)&XL[sl * LDX + c0] = make_uint4(lp[0], lp[1], lp[2], lp[3]);
        }
        PN[sl * 4 + q] = ss;
        __syncthreads();                         // S1: XH/XL + PN ready

        // norm column (c=128): ||x_s|| hi/lo (warp 0, 2 s per lane)
        if (tid < 32) {
            #pragma unroll
            for (int h2 = 0; h2 < 2; h2++) {
                int s = l + h2 * 32;
                float a = PN[s*4] + PN[s*4+1] + PN[s*4+2] + PN[s*4+3];
                float nrm = fmaxf(sqrtf(a), 1e-12f);
                __nv_bfloat16 hh = __float2bfloat16(nrm);
                XH[s * LDX + 128] = hh;
                XL[s * LDX + 128] = __float2bfloat16(nrm - __bfloat162float(hh));
            }
        }

        // ---- GEMM1 on RAW x: warp = m16 stripe x 32 clusters (K-half) ----
        float lacc[4][4];
        #pragma unroll
        for (int j = 0; j < 4; j++)
            #pragma unroll
            for (int p = 0; p < 4; p++) lacc[j][p] = 0.0f;
        {
            uint32_t aoffA = (uint32_t)(((m0g1 + (l & 15)) * LDX + ((l >> 4) << 3)) * 2);
            uint32_t boffB = (uint32_t)(((((l >> 4) << 3) + (l & 7) + kh * 32) * LDW
                                        + (((l >> 3) & 1) << 3)) * 2);
            #pragma unroll 1
            for (int kc = 0; kc < 8; kc++) {
                uint32_t axh[4], axl[4];
                ldsm4(axh, XHu + aoffA + kc * 32);
                ldsm4(axl, XLu + aoffA + kc * 32);
                #pragma unroll
                for (int j = 0; j < 2; j++) {
                    uint32_t bwh[4], bwl[4];
                    uint32_t bo = boffB + kc * 32 + j * 16 * LDW * 2;
                    ldsm4(bwh, WHu + bo);
                    ldsm4(bwl, WLu + bo);
                    mma_bf16(lacc[2*j],   axh, bwh[0], bwh[1]);
                    mma_bf16(lacc[2*j+1], axh, bwh[2], bwh[3]);
                    mma_bf16(lacc[2*j],   axl, bwh[0], bwh[1]);
                    mma_bf16(lacc[2*j+1], axl, bwh[2], bwh[3]);
                    mma_bf16(lacc[2*j],   axh, bwl[0], bwl[1]);
                    mma_bf16(lacc[2*j+1], axh, bwl[2], bwl[3]);
                }
            }
        }

        // ---- post-scale + softmax (no max-shift; logits bounded) ----
        {
            const int r0 = m0g1 + (l >> 2);
            float s40 = PN[r0*4] + PN[r0*4+1] + PN[r0*4+2] + PN[r0*4+3];
            float s41 = PN[(r0+8)*4] + PN[(r0+8)*4+1]
                      + PN[(r0+8)*4+2] + PN[(r0+8)*4+3];
            float sc0 = 1.0f / fmaxf(sqrtf(s40), 1e-12f);
            float sc1 = 1.0f / fmaxf(sqrtf(s41), 1e-12f);

            float se0 = 0.0f, se1 = 0.0f;
            #pragma unroll
            for (int j = 0; j < 4; j++) {
                float e;
                e = __expf(fmaf(lacc[j][0], sc0, bias_r[j][0])); lacc[j][0] = e; se0 += e;
                e = __expf(fmaf(lacc[j][1], sc0, bias_r[j][1])); lacc[j][1] = e; se0 += e;
                e = __expf(fmaf(lacc[j][2], sc1, bias_r[j][0])); lacc[j][2] = e; se1 += e;
                e = __expf(fmaf(lacc[j][3], sc1, bias_r[j][1])); lacc[j][3] = e; se1 += e;
            }
            se0 += __shfl_xor_sync(0xffffffffu, se0, 1);
            se0 += __shfl_xor_sync(0xffffffffu, se0, 2);
            se1 += __shfl_xor_sync(0xffffffffu, se1, 1);
            se1 += __shfl_xor_sync(0xffffffffu, se1, 2);
            if ((l & 3) == 0) {
                PS[r0 * 2 + kh]       = se0;
                PS[(r0 + 8) * 2 + kh] = se1;
            }
            // pairwise exchange between warps (w) and (w+4) only
            asm volatile("bar.sync %0, 64;" :: "r"((w & 3) + 1) : "memory");

            float inv0 = sc0 / (PS[r0 * 2] + PS[r0 * 2 + 1]);
            float inv1 = sc1 / (PS[(r0 + 8) * 2] + PS[(r0 + 8) * 2 + 1]);

            // soft stored [s][k]: conflict-free bf16x2 stores
            #pragma unroll
            for (int j = 0; j < 4; j++) {
                int k0 = kh * 32 + j * 8 + cst;
                float v00 = lacc[j][0] * inv0, v01 = lacc[j][1] * inv0;
                float v10 = lacc[j][2] * inv1, v11 = lacc[j][3] * inv1;
                *(uint32_t*)&SHm[r0 * LDK + k0] = bf2_pack(v00, v01);
                *(uint32_t*)&SHm[(r0 + 8) * LDK + k0] = bf2_pack(v10, v11);
                __nv_bfloat16 h00 = __float2bfloat16(v00);
                __nv_bfloat16 h01 = __float2bfloat16(v01);
                __nv_bfloat16 h10 = __float2bfloat16(v10);
                __nv_bfloat16 h11 = __float2bfloat16(v11);
                *(uint32_t*)&SLm[r0 * LDK + k0] =
                    bf2_pack(v00 - __bfloat162float(h00),
                             v01 - __bfloat162float(h01));
                *(uint32_t*)&SLm[(r0 + 8) * LDK + k0] =
                    bf2_pack(v10 - __bfloat162float(h10),
                             v11 - __bfloat162float(h11));
            }
        }
        __syncthreads();                         // S2: soft + norm col ready

        // ---- GEMM2: warp = k32 half x c32 quarter; ldsm4t everywhere ----
        #pragma unroll 1
        for (int ks = 0; ks < 4; ks++) {
            int sb = ks * 16;
            // A = soft^T: two m16 tiles
            uint32_t ash[2][4], asl[2][4];
            #pragma unroll
            for (int mi = 0; mi < 2; mi++) {
                uint32_t aoff = (uint32_t)(((sb + (l & 15)) * LDK + m0b + mi * 16
                                           + ((l >> 4) << 3)) * 2);
                uint32_t th[4], tl[4];
                ldsm4t(th, SHu + aoff);
                ldsm4t(tl, SLu + aoff);
                ash[mi][0] = th[0]; ash[mi][1] = th[2];
                ash[mi][2] = th[1]; ash[mi][3] = th[3];
                asl[mi][0] = tl[0]; asl[mi][1] = tl[2];
                asl[mi][2] = tl[1]; asl[mi][3] = tl[3];
            }
            // B = x: two ldsm4t cover n=32 (16 cols each)
            #pragma unroll
            for (int half = 0; half < 2; half++) {
                int n0 = nb + half * 16;
                uint32_t boff = (uint32_t)(((sb + (l & 15)) * LDX + n0
                                           + ((l >> 4) << 3)) * 2);
                uint32_t bxh[4], bxl[4];
                ldsm4t(bxh, XHu + boff);
                ldsm4t(bxl, XLu + boff);
                #pragma unroll
                for (int mi = 0; mi < 2; mi++) {
                    int j0 = half * 2;
                    mma_bf16(vacc[mi][j0],     ash[mi], bxh[0], bxh[1]);
                    mma_bf16(vacc[mi][j0],     asl[mi], bxh[0], bxh[1]);
                    mma_bf16(vacc[mi][j0],     ash[mi], bxl[0], bxl[1]);
                    mma_bf16(vacc[mi][j0 + 1], ash[mi], bxh[2], bxh[3]);
                    mma_bf16(vacc[mi][j0 + 1], asl[mi], bxh[2], bxh[3]);
                    mma_bf16(vacc[mi][j0 + 1], ash[mi], bxl[2], bxl[3]);
                }
            }
            if (nb == 96) {   // norm column at c=128 -> a_sum
                uint32_t boffN = (uint32_t)(((sb + (l & 15)) * LDX + 128) * 2);
                uint32_t nh0, nh1, nl0, nl1;
                ldsm2t(nh0, nh1, XHu + boffN);
                ldsm2t(nl0, nl1, XLu + boffN);
                #pragma unroll
                for (int mi = 0; mi < 2; mi++) {
                    mma_bf16(vacc8[mi], ash[mi], nh0, nh1);
                    mma_bf16(vacc8[mi], asl[mi], nh0, nh1);
                    mma_bf16(vacc8[mi], ash[mi], nl0, nl1);
                }
            }
        }
    }

    // ---- write per-block partial (no atomics) ----
    float* vdst = g_part + (size_t)blockIdx.x * PSTRIDE;
    {
        #pragma unroll
        for (int mi = 0; mi < 2; mi++) {
            int r0 = m0b + mi * 16 + (l >> 2);
            #pragma unroll
            for (int j = 0; j < 4; j++) {
                int c = nb + j * 8 + cst;
                vdst[r0 * C_ + c]           = vacc[mi][j][0];
                vdst[r0 * C_ + c + 1]       = vacc[mi][j][1];
                vdst[(r0 + 8) * C_ + c]     = vacc[mi][j][2];
                vdst[(r0 + 8) * C_ + c + 1] = vacc[mi][j][3];
            }
            if (nb == 96 && (l & 3) == 0) {
                vdst[8192 + r0]     = vacc8[mi][0];
                vdst[8192 + r0 + 8] = vacc8[mi][2];
            }
        }
    }
}

// ---------------------------------------------------------------------------
// Wide parallel reduction: 256 partials -> 16.
#define REDV (PSTRIDE / 4)            // 2064 float4 per n
__global__ __launch_bounds__(256)
void nv_reduce_kernel() {
    int idx = blockIdx.x * 256 + threadIdx.x;
    if (idx >= N_ * REDV) return;
    int n  = idx / REDV;
    int e4 = idx - n * REDV;
    const float4* pb = (const float4*)(g_part + (size_t)n * SGROUPS * PSTRIDE)
                       + e4;
    float4 s = make_float4(0.f, 0.f, 0.f, 0.f);
    #pragma unroll 8
    for (int p = 0; p < SGROUPS; p++) {
        float4 v = pb[(size_t)p * (PSTRIDE / 4)];
        s.x += v.x; s.y += v.y; s.z += v.z; s.w += v.w;
    }
    ((float4*)(g_red + (size_t)n * PSTRIDE))[e4] = s;
}

// ---------------------------------------------------------------------------
__global__ __launch_bounds__(256)
void nv_finalize_kernel(const float* __restrict__ centroids,
                        float* __restrict__ out) {
    __shared__ float vsh[K_ * C_];
    __shared__ float ash[K_];
    __shared__ float wsum[8];

    const int n   = blockIdx.x;
    const int tid = threadIdx.x;
    const float* rb = g_red + (size_t)n * PSTRIDE;

    for (int e = tid * 4; e < K_ * C_; e += 256 * 4)
        *(float4*)&vsh[e] = *(const float4*)&rb[e];
    if (tid < K_) ash[tid] = rb[8192 + tid];
    __syncthreads();

    const int k  = tid >> 2;
    const int cb = (tid & 3) * 32;
    const float ak = ash[k];

    float ssk = 0.0f;
    #pragma unroll 8
    for (int c = 0; c < 32; c++) {
        int idx = k * C_ + cb + c;
        float v = vsh[idx] - ak * centroids[idx];
        vsh[idx] = v;
        ssk = fmaf(v, v, ssk);
    }
    ssk += __shfl_xor_sync(0xffffffffu, ssk, 1);
    ssk += __shfl_xor_sync(0xffffffffu, ssk, 2);
    float rinv = 1.0f / fmaxf(sqrtf(ssk), 1e-12f);

    float tot = 0.0f;
    #pragma unroll 8
    for (int c = 0; c < 32; c++) {
        int idx = k * C_ + cb + c;
        float tv = vsh[idx] * rinv;
        vsh[idx] = tv;
        tot = fmaf(tv, tv, tot);
    }
    #pragma unroll
    for (int off = 16; off > 0; off >>= 1)
        tot += __shfl_xor_sync(0xffffffffu, tot, off);
    if ((tid & 31) == 0) wsum[tid >> 5] = tot;
    __syncthreads();
    float total = 0.0f;
    #pragma unroll
    for (int i = 0; i < 8; i++) total += wsum[i];
    float ginv = 1.0f / fmaxf(sqrtf(total), 1e-12f);

    float* od = out + (size_t)n * K_ * C_;
    for (int i = tid; i < K_ * C_; i += 256)
        od[i] = vsh[i] * ginv;
}

// ---------------------------------------------------------------------------
extern "C" void kernel_launch(void* const* d_in, const int* in_sizes, int n_in,
                              void* d_out, int out_size) {
    const float* x         = (const float*)d_in[0];
    const float* fc_w      = (const float*)d_in[1];
    const float* fc_b      = (const float*)d_in[2];
    const float* centroids = (const float*)d_in[3];
    float* out = (float*)d_out;

    cudaFuncSetAttribute(nv_main_kernel,
                         cudaFuncAttributeMaxDynamicSharedMemorySize,
                         SMEM_TOT);

    nv_main_kernel<<<NBLK, NTH, SMEM_TOT>>>(x, fc_w, fc_b);
    nv_reduce_kernel<<<(N_ * REDV + 255) / 256, 256>>>();
    nv_finalize_kernel<<<N_, 256>>>(centroids, out);
}

// round 13
// speedup vs baseline: 1.2589x; 1.2589x over previous
#include <cuda_runtime.h>
#include <cuda_bf16.h>
#include <math.h>
#include <stdint.h>

#define N_  16
#define C_  128
#define S_  16384
#define K_  64
#define TS  64
#define TILES 16
#define SGROUPS (S_ / (TS * TILES))   // 16
#define NBLK (N_ * SGROUPS)           // 256
#define NTH 256
#define LDX 136   // bf16 row stride x tiles [s][c] (col 128 = ||x|| hi/lo)
#define LDW 136
#define LDK 72    // bf16 row stride soft [s][k]
#define PSTRIDE 8256                  // 8192 vacc + 64 asum per block partial

__device__ float g_part[NBLK * PSTRIDE];
__device__ float g_red[N_ * PSTRIDE];

// ---------------------------------------------------------------------------
__device__ __forceinline__ uint32_t s2u(const void* p) {
    uint32_t a;
    asm("{ .reg .u64 t; cvta.to.shared.u64 t, %1; cvt.u32.u64 %0, t; }"
        : "=r"(a) : "l"(p));
    return a;
}
__device__ __forceinline__ void ldsm4(uint32_t* r, uint32_t addr) {
    asm volatile("ldmatrix.sync.aligned.m8n8.x4.shared.b16 {%0,%1,%2,%3}, [%4];"
                 : "=r"(r[0]), "=r"(r[1]), "=r"(r[2]), "=r"(r[3]) : "r"(addr));
}
__device__ __forceinline__ void ldsm4t(uint32_t* r, uint32_t addr) {
    asm volatile("ldmatrix.sync.aligned.m8n8.x4.trans.shared.b16 {%0,%1,%2,%3}, [%4];"
                 : "=r"(r[0]), "=r"(r[1]), "=r"(r[2]), "=r"(r[3]) : "r"(addr));
}
__device__ __forceinline__ void ldsm2t(uint32_t& r0, uint32_t& r1, uint32_t addr) {
    asm volatile("ldmatrix.sync.aligned.m8n8.x2.trans.shared.b16 {%0,%1}, [%2];"
                 : "=r"(r0), "=r"(r1) : "r"(addr));
}
__device__ __forceinline__ void mma_bf16(float* d, const uint32_t* a,
                                         uint32_t b0, uint32_t b1) {
    asm volatile("mma.sync.aligned.m16n8k16.row.col.f32.bf16.bf16.f32 "
                 "{%0,%1,%2,%3}, {%4,%5,%6,%7}, {%8,%9}, {%0,%1,%2,%3};"
                 : "+f"(d[0]), "+f"(d[1]), "+f"(d[2]), "+f"(d[3])
                 : "r"(a[0]), "r"(a[1]), "r"(a[2]), "r"(a[3]), "r"(b0), "r"(b1));
}
__device__ __forceinline__ uint32_t bf2_pack(float lo, float hi) {
    __nv_bfloat162 p;
    p.x = __float2bfloat16(lo); p.y = __float2bfloat16(hi);
    return *(uint32_t*)&p;
}

// ---------------------------------------------------------------------------
// smem byte offsets (ldsm bases 128-aligned)
#define OFF_XH   0
#define OFF_XL   17408
#define OFF_WH   34816
#define OFF_WL   52224
#define OFF_SH   69632        // soft hi [s][k] 64 x 72 bf16
#define OFF_BB   78848
#define OFF_PN   79104        // float[64][4]
#define OFF_PS   80128        // float[64][2]
#define SMEM_TOT 80640

__global__ __launch_bounds__(NTH, 2)
void nv_main_kernel(const float* __restrict__ x,
                    const float* __restrict__ fc_w,
                    const float* __restrict__ fc_b) {
    extern __shared__ char smem[];
    __nv_bfloat16* XH  = (__nv_bfloat16*)(smem + OFF_XH);
    __nv_bfloat16* XL  = (__nv_bfloat16*)(smem + OFF_XL);
    __nv_bfloat16* WH  = (__nv_bfloat16*)(smem + OFF_WH);
    __nv_bfloat16* WL  = (__nv_bfloat16*)(smem + OFF_WL);
    __nv_bfloat16* SHm = (__nv_bfloat16*)(smem + OFF_SH);
    float* BB = (float*)(smem + OFF_BB);
    float* PN = (float*)(smem + OFF_PN);
    float* PS = (float*)(smem + OFF_PS);

    const uint32_t XHu = s2u(XH), XLu = s2u(XL), WHu = s2u(WH), WLu = s2u(WL);
    const uint32_t SHu = s2u(SHm);

    const int n   = blockIdx.x >> 4;
    const int g   = blockIdx.x & (SGROUPS - 1);
    const int tid = threadIdx.x;
    const int l   = tid & 31;
    const int w   = tid >> 5;            // 0..7
    const int sl  = tid & 63;            // position (load/convert)
    const int q   = tid >> 6;            // channel quarter 0..3

    // GEMM1 split: m-stripe (w&3) over s, K-half kh (w>>2)
    const int m0g1 = (w & 3) * 16;
    const int kh   = w >> 2;
    // GEMM2 split: k-stripe (w&3), c-half (w>>2)*64
    const int m0b  = (w & 3) * 16;
    const int nb   = (w >> 2) * 64;

    // ---- load fc_w hi/lo + bias (once per block) ----
    for (int i = tid; i < K_ * C_; i += NTH) {
        int k = i >> 7, c = i & 127;
        float v = fc_w[i];
        __nv_bfloat16 hi = __float2bfloat16(v);
        WH[k * LDW + c] = hi;
        WL[k * LDW + c] = __float2bfloat16(v - __bfloat162float(hi));
    }
    if (tid < K_) BB[tid] = fc_b[tid];
    __syncthreads();

    const int cst = (l & 3) * 2;
    float bias_r[4][2];
    #pragma unroll
    for (int j = 0; j < 4; j++) {
        bias_r[j][0] = BB[kh * 32 + j * 8 + cst];
        bias_r[j][1] = BB[kh * 32 + j * 8 + cst + 1];
    }

    float vacc[8][4];
    #pragma unroll
    for (int j = 0; j < 8; j++)
        #pragma unroll
        for (int p = 0; p < 4; p++) vacc[j][p] = 0.0f;
    float vacc8[4] = {0.f, 0.f, 0.f, 0.f};   // norm-column (a_sum)

    #pragma unroll 1
    for (int t = 0; t < TILES; t++) {
        const int s0 = g * (TS * TILES) + t * TS;
        const float* xg = x + (size_t)n * C_ * S_ + s0;
        __syncthreads();                         // A: prev tile consumers done

        // ---- convert: 16B-chunk stores (conflict-free STS.128) ----
        float ss = 0.0f;
        #pragma unroll
        for (int ch = 0; ch < 4; ch++) {
            const int c0 = q * 32 + ch * 8;
            uint32_t hp[4], lp[4];
            #pragma unroll
            for (int u = 0; u < 4; u++) {
                float v0 = xg[(size_t)(c0 + 2*u)     * S_ + sl];
                float v1 = xg[(size_t)(c0 + 2*u + 1) * S_ + sl];
                ss = fmaf(v0, v0, ss); ss = fmaf(v1, v1, ss);
                __nv_bfloat16 h0 = __float2bfloat16(v0);
                __nv_bfloat16 h1 = __float2bfloat16(v1);
                __nv_bfloat162 hv; hv.x = h0; hv.y = h1;
                hp[u] = *(uint32_t*)&hv;
                lp[u] = bf2_pack(v0 - __bfloat162float(h0),
                                 v1 - __bfloat162float(h1));
            }
            *(uint4*)&XH[sl * LDX + c0] = make_uint4(hp[0], hp[1], hp[2], hp[3]);
            *(uint4*)&XL[sl * LDX + c0] = make_uint4(lp[0], lp[1], lp[2], lp[3]);
        }
        PN[sl * 4 + q] = ss;
        __syncthreads();                         // S1: XH/XL + PN ready

        // norm column (c=128): ||x_s|| hi/lo (warp 0, 2 s per lane)
        if (tid < 32) {
            #pragma unroll
            for (int h2 = 0; h2 < 2; h2++) {
                int s = l + h2 * 32;
                float a = PN[s*4] + PN[s*4+1] + PN[s*4+2] + PN[s*4+3];
                float nrm = fmaxf(sqrtf(a), 1e-12f);
                __nv_bfloat16 hh = __float2bfloat16(nrm);
                XH[s * LDX + 128] = hh;
                XL[s * LDX + 128] = __float2bfloat16(nrm - __bfloat162float(hh));
            }
        }

        // ---- GEMM1 on RAW x: warp = m16 stripe x 32 clusters (K-half) ----
        float lacc[4][4];
        #pragma unroll
        for (int j = 0; j < 4; j++)
            #pragma unroll
            for (int p = 0; p < 4; p++) lacc[j][p] = 0.0f;
        {
            uint32_t aoffA = (uint32_t)(((m0g1 + (l & 15)) * LDX + ((l >> 4) << 3)) * 2);
            uint32_t boffB = (uint32_t)(((((l >> 4) << 3) + (l & 7) + kh * 32) * LDW
                                        + (((l >> 3) & 1) << 3)) * 2);
            #pragma unroll 1
            for (int kc = 0; kc < 8; kc++) {
                uint32_t axh[4], axl[4];
                ldsm4(axh, XHu + aoffA + kc * 32);
                ldsm4(axl, XLu + aoffA + kc * 32);
                #pragma unroll
                for (int j = 0; j < 2; j++) {
                    uint32_t bwh[4], bwl[4];
                    uint32_t bo = boffB + kc * 32 + j * 16 * LDW * 2;
                    ldsm4(bwh, WHu + bo);
                    ldsm4(bwl, WLu + bo);
                    mma_bf16(lacc[2*j],   axh, bwh[0], bwh[1]);
                    mma_bf16(lacc[2*j+1], axh, bwh[2], bwh[3]);
                    mma_bf16(lacc[2*j],   axl, bwh[0], bwh[1]);
                    mma_bf16(lacc[2*j+1], axl, bwh[2], bwh[3]);
                    mma_bf16(lacc[2*j],   axh, bwl[0], bwl[1]);
                    mma_bf16(lacc[2*j+1], axh, bwl[2], bwl[3]);
                }
            }
        }

        // ---- post-scale + softmax (no max-shift; logits bounded) ----
        {
            const int r0 = m0g1 + (l >> 2);
            float s40 = PN[r0*4] + PN[r0*4+1] + PN[r0*4+2] + PN[r0*4+3];
            float s41 = PN[(r0+8)*4] + PN[(r0+8)*4+1]
                      + PN[(r0+8)*4+2] + PN[(r0+8)*4+3];
            float sc0 = 1.0f / fmaxf(sqrtf(s40), 1e-12f);
            float sc1 = 1.0f / fmaxf(sqrtf(s41), 1e-12f);

            float se0 = 0.0f, se1 = 0.0f;
            #pragma unroll
            for (int j = 0; j < 4; j++) {
                float e;
                e = __expf(fmaf(lacc[j][0], sc0, bias_r[j][0])); lacc[j][0] = e; se0 += e;
                e = __expf(fmaf(lacc[j][1], sc0, bias_r[j][1])); lacc[j][1] = e; se0 += e;
                e = __expf(fmaf(lacc[j][2], sc1, bias_r[j][0])); lacc[j][2] = e; se1 += e;
                e = __expf(fmaf(lacc[j][3], sc1, bias_r[j][1])); lacc[j][3] = e; se1 += e;
            }
            se0 += __shfl_xor_sync(0xffffffffu, se0, 1);
            se0 += __shfl_xor_sync(0xffffffffu, se0, 2);
            se1 += __shfl_xor_sync(0xffffffffu, se1, 1);
            se1 += __shfl_xor_sync(0xffffffffu, se1, 2);
            if ((l & 3) == 0) {
                PS[r0 * 2 + kh]       = se0;
                PS[(r0 + 8) * 2 + kh] = se1;
            }
            // pairwise exchange between warps (w) and (w+4) only
            asm volatile("bar.sync %0, 64;" :: "r"((w & 3) + 1) : "memory");

            float inv0 = sc0 / (PS[r0 * 2] + PS[r0 * 2 + 1]);
            float inv1 = sc1 / (PS[(r0 + 8) * 2] + PS[(r0 + 8) * 2 + 1]);

            // soft stored [s][k] hi-only: conflict-free bf16x2 stores
            #pragma unroll
            for (int j = 0; j < 4; j++) {
                int k0 = kh * 32 + j * 8 + cst;
                *(uint32_t*)&SHm[r0 * LDK + k0] =
                    bf2_pack(lacc[j][0] * inv0, lacc[j][1] * inv0);
                *(uint32_t*)&SHm[(r0 + 8) * LDK + k0] =
                    bf2_pack(lacc[j][2] * inv1, lacc[j][3] * inv1);
            }
        }
        __syncthreads();                         // S2: soft + norm col ready

        // ---- GEMM2 single-term: A = soft^T (ldsm4t), B = x hi (ldsm2t) ----
        #pragma unroll 1
        for (int ks = 0; ks < 4; ks++) {
            int sb = ks * 16;
            uint32_t aoff = (uint32_t)(((sb + (l & 15)) * LDK + m0b
                                       + ((l >> 4) << 3)) * 2);
            uint32_t th[4], ash[4];
            ldsm4t(th, SHu + aoff);
            ash[0] = th[0]; ash[1] = th[2]; ash[2] = th[1]; ash[3] = th[3];
            uint32_t boff = (uint32_t)(((sb + (l & 15)) * LDX) * 2);
            #pragma unroll
            for (int j = 0; j < 8; j++) {
                int n0 = nb + j * 8;
                uint32_t bxh0, bxh1;
                ldsm2t(bxh0, bxh1, XHu + boff + n0 * 2);
                mma_bf16(vacc[j], ash, bxh0, bxh1);
            }
            if (nb == 64) {   // norm column at c=128 -> a_sum (2-term)
                uint32_t nh0, nh1, nl0, nl1;
                ldsm2t(nh0, nh1, XHu + boff + 128 * 2);
                ldsm2t(nl0, nl1, XLu + boff + 128 * 2);
                mma_bf16(vacc8, ash, nh0, nh1);
                mma_bf16(vacc8, ash, nl0, nl1);
            }
        }
    }

    // ---- write per-block partial (no atomics) ----
    float* vdst = g_part + (size_t)blockIdx.x * PSTRIDE;
    {
        int r0 = m0b + (l >> 2);
        #pragma unroll
        for (int j = 0; j < 8; j++) {
            int c = nb + j * 8 + cst;
            vdst[r0 * C_ + c]           = vacc[j][0];
            vdst[r0 * C_ + c + 1]       = vacc[j][1];
            vdst[(r0 + 8) * C_ + c]     = vacc[j][2];
            vdst[(r0 + 8) * C_ + c + 1] = vacc[j][3];
        }
        if (nb == 64 && (l & 3) == 0) {
            vdst[8192 + r0]     = vacc8[0];
            vdst[8192 + r0 + 8] = vacc8[2];
        }
    }
}

// ---------------------------------------------------------------------------
// Wide parallel reduction: 256 partials -> 16.
#define REDV (PSTRIDE / 4)            // 2064 float4 per n
__global__ __launch_bounds__(256)
void nv_reduce_kernel() {
    int idx = blockIdx.x * 256 + threadIdx.x;
    if (idx >= N_ * REDV) return;
    int n  = idx / REDV;
    int e4 = idx - n * REDV;
    const float4* pb = (const float4*)(g_part + (size_t)n * SGROUPS * PSTRIDE)
                       + e4;
    float4 s = make_float4(0.f, 0.f, 0.f, 0.f);
    #pragma unroll 8
    for (int p = 0; p < SGROUPS; p++) {
        float4 v = pb[(size_t)p * (PSTRIDE / 4)];
        s.x += v.x; s.y += v.y; s.z += v.z; s.w += v.w;
    }
    ((float4*)(g_red + (size_t)n * PSTRIDE))[e4] = s;
}

// ---------------------------------------------------------------------------
__global__ __launch_bounds__(256)
void nv_finalize_kernel(const float* __restrict__ centroids,
                        float* __restrict__ out) {
    __shared__ float vsh[K_ * C_];
    __shared__ float ash[K_];
    __shared__ float wsum[8];

    const int n   = blockIdx.x;
    const int tid = threadIdx.x;
    const float* rb = g_red + (size_t)n * PSTRIDE;

    for (int e = tid * 4; e < K_ * C_; e += 256 * 4)
        *(float4*)&vsh[e] = *(const float4*)&rb[e];
    if (tid < K_) ash[tid] = rb[8192 + tid];
    __syncthreads();

    const int k  = tid >> 2;
    const int cb = (tid & 3) * 32;
    const float ak = ash[k];

    float ssk = 0.0f;
    #pragma unroll 8
    for (int c = 0; c < 32; c++) {
        int idx = k * C_ + cb + c;
        float v = vsh[idx] - ak * centroids[idx];
        vsh[idx] = v;
        ssk = fmaf(v, v, ssk);
    }
    ssk += __shfl_xor_sync(0xffffffffu, ssk, 1);
    ssk += __shfl_xor_sync(0xffffffffu, ssk, 2);
    float rinv = 1.0f / fmaxf(sqrtf(ssk), 1e-12f);

    float tot = 0.0f;
    #pragma unroll 8
    for (int c = 0; c < 32; c++) {
        int idx = k * C_ + cb + c;
        float tv = vsh[idx] * rinv;
        vsh[idx] = tv;
        tot = fmaf(tv, tv, tot);
    }
    #pragma unroll
    for (int off = 16; off > 0; off >>= 1)
        tot += __shfl_xor_sync(0xffffffffu, tot, off);
    if ((tid & 31) == 0) wsum[tid >> 5] = tot;
    __syncthreads();
    float total = 0.0f;
    #pragma unroll
    for (int i = 0; i < 8; i++) total += wsum[i];
    float ginv = 1.0f / fmaxf(sqrtf(total), 1e-12f);

    float* od = out + (size_t)n * K_ * C_;
    for (int i = tid; i < K_ * C_; i += 256)
        od[i] = vsh[i] * ginv;
}

// ---------------------------------------------------------------------------
extern "C" void kernel_launch(void* const* d_in, const int* in_sizes, int n_in,
                              void* d_out, int out_size) {
    const float* x         = (const float*)d_in[0];
    const float* fc_w      = (const float*)d_in[1];
    const float* fc_b      = (const float*)d_in[2];
    const float* centroids = (const float*)d_in[3];
    float* out = (float*)d_out;

    cudaFuncSetAttribute(nv_main_kernel,
                         cudaFuncAttributeMaxDynamicSharedMemorySize,
                         SMEM_TOT);

    nv_main_kernel<<<NBLK, NTH, SMEM_TOT>>>(x, fc_w, fc_b);
    nv_reduce_kernel<<<(N_ * REDV + 255) / 256, 256>>>();
    nv_finalize_kernel<<<N_, 256>>>(centroids, out);
}

// round 14
// speedup vs baseline: 1.4896x; 1.1833x over previous
#include <cuda_runtime.h>
#include <cuda_bf16.h>
#include <math.h>
#include <stdint.h>

#define N_  16
#define C_  128
#define S_  16384
#define K_  64
#define TS  64
#define TILES 16
#define SGROUPS (S_ / (TS * TILES))   // 16
#define NBLK (N_ * SGROUPS)           // 256
#define NTH 256
#define LDX 136   // bf16 row stride x tiles [s][c] (col 128 = ||x|| hi)
#define LDW 136
#define LDK 72    // bf16 row stride soft [s][k]
#define PSTRIDE 8256                  // 8192 vacc + 64 asum per block partial

__device__ float g_part[NBLK * PSTRIDE];
__device__ float g_red[N_ * PSTRIDE];

// ---------------------------------------------------------------------------
__device__ __forceinline__ uint32_t s2u(const void* p) {
    uint32_t a;
    asm("{ .reg .u64 t; cvta.to.shared.u64 t, %1; cvt.u32.u64 %0, t; }"
        : "=r"(a) : "l"(p));
    return a;
}
__device__ __forceinline__ void ldsm4(uint32_t* r, uint32_t addr) {
    asm volatile("ldmatrix.sync.aligned.m8n8.x4.shared.b16 {%0,%1,%2,%3}, [%4];"
                 : "=r"(r[0]), "=r"(r[1]), "=r"(r[2]), "=r"(r[3]) : "r"(addr));
}
__device__ __forceinline__ void ldsm4t(uint32_t* r, uint32_t addr) {
    asm volatile("ldmatrix.sync.aligned.m8n8.x4.trans.shared.b16 {%0,%1,%2,%3}, [%4];"
                 : "=r"(r[0]), "=r"(r[1]), "=r"(r[2]), "=r"(r[3]) : "r"(addr));
}
__device__ __forceinline__ void ldsm2t(uint32_t& r0, uint32_t& r1, uint32_t addr) {
    asm volatile("ldmatrix.sync.aligned.m8n8.x2.trans.shared.b16 {%0,%1}, [%2];"
                 : "=r"(r0), "=r"(r1) : "r"(addr));
}
__device__ __forceinline__ void mma_bf16(float* d, const uint32_t* a,
                                         uint32_t b0, uint32_t b1) {
    asm volatile("mma.sync.aligned.m16n8k16.row.col.f32.bf16.bf16.f32 "
                 "{%0,%1,%2,%3}, {%4,%5,%6,%7}, {%8,%9}, {%0,%1,%2,%3};"
                 : "+f"(d[0]), "+f"(d[1]), "+f"(d[2]), "+f"(d[3])
                 : "r"(a[0]), "r"(a[1]), "r"(a[2]), "r"(a[3]), "r"(b0), "r"(b1));
}
__device__ __forceinline__ uint32_t bf2_pack(float lo, float hi) {
    __nv_bfloat162 p;
    p.x = __float2bfloat16(lo); p.y = __float2bfloat16(hi);
    return *(uint32_t*)&p;
}

// ---------------------------------------------------------------------------
// smem byte offsets (ldsm bases 128-aligned)
#define OFF_XH   0            // 64 x 136 bf16 = 17408
#define OFF_WH   17408        // 64 x 136 bf16 = 17408
#define OFF_SH   34816        // soft hi [s][k] 64 x 72 bf16 = 9216
#define OFF_NL   44032        // norm-lo [64][8] bf16 = 1024
#define OFF_BB   45056        // 64 f32
#define OFF_PN   45312        // float[64][4]
#define OFF_PS   46336        // float[64][2]
#define SMEM_TOT 46848

__global__ __launch_bounds__(NTH, 2)
void nv_main_kernel(const float* __restrict__ x,
                    const float* __restrict__ fc_w,
                    const float* __restrict__ fc_b) {
    extern __shared__ char smem[];
    __nv_bfloat16* XH  = (__nv_bfloat16*)(smem + OFF_XH);
    __nv_bfloat16* WH  = (__nv_bfloat16*)(smem + OFF_WH);
    __nv_bfloat16* SHm = (__nv_bfloat16*)(smem + OFF_SH);
    __nv_bfloat16* NLm = (__nv_bfloat16*)(smem + OFF_NL);
    float* BB = (float*)(smem + OFF_BB);
    float* PN = (float*)(smem + OFF_PN);
    float* PS = (float*)(smem + OFF_PS);

    const uint32_t XHu = s2u(XH), WHu = s2u(WH);
    const uint32_t SHu = s2u(SHm), NLu = s2u(NLm);

    const int n   = blockIdx.x >> 4;
    const int g   = blockIdx.x & (SGROUPS - 1);
    const int tid = threadIdx.x;
    const int l   = tid & 31;
    const int w   = tid >> 5;            // 0..7
    const int sl  = tid & 63;            // position (load/convert)
    const int q   = tid >> 6;            // channel quarter 0..3

    // GEMM1 split: m-stripe (w&3) over s, K-half kh (w>>2)
    const int m0g1 = (w & 3) * 16;
    const int kh   = w >> 2;
    // GEMM2 split: k-stripe (w&3), c-half (w>>2)*64
    const int m0b  = (w & 3) * 16;
    const int nb   = (w >> 2) * 64;

    // ---- load fc_w hi + bias (once per block) ----
    for (int i = tid; i < K_ * C_; i += NTH) {
        int k = i >> 7, c = i & 127;
        WH[k * LDW + c] = __float2bfloat16(fc_w[i]);
    }
    if (tid < K_) BB[tid] = fc_b[tid];
    __syncthreads();

    const int cst = (l & 3) * 2;
    float bias_r[4][2];
    #pragma unroll
    for (int j = 0; j < 4; j++) {
        bias_r[j][0] = BB[kh * 32 + j * 8 + cst];
        bias_r[j][1] = BB[kh * 32 + j * 8 + cst + 1];
    }

    float vacc[8][4];
    #pragma unroll
    for (int j = 0; j < 8; j++)
        #pragma unroll
        for (int p = 0; p < 4; p++) vacc[j][p] = 0.0f;
    float vacc8[4] = {0.f, 0.f, 0.f, 0.f};   // norm-column (a_sum)

    #pragma unroll 1
    for (int t = 0; t < TILES; t++) {
        const int s0 = g * (TS * TILES) + t * TS;
        const float* xg = x + (size_t)n * C_ * S_ + s0;
        __syncthreads();                         // A: prev tile consumers done

        // ---- convert: hi-only 16B-chunk stores (conflict-free STS.128) ----
        float ss = 0.0f;
        #pragma unroll
        for (int ch = 0; ch < 4; ch++) {
            const int c0 = q * 32 + ch * 8;
            uint32_t hp[4];
            #pragma unroll
            for (int u = 0; u < 4; u++) {
                float v0 = xg[(size_t)(c0 + 2*u)     * S_ + sl];
                float v1 = xg[(size_t)(c0 + 2*u + 1) * S_ + sl];
                ss = fmaf(v0, v0, ss); ss = fmaf(v1, v1, ss);
                hp[u] = bf2_pack(v0, v1);
            }
            *(uint4*)&XH[sl * LDX + c0] = make_uint4(hp[0], hp[1], hp[2], hp[3]);
        }
        PN[sl * 4 + q] = ss;
        __syncthreads();                         // S1: XH + PN ready

        // norm column (c=128): ||x_s|| hi in XH, lo in NL (warp 0)
        if (tid < 32) {
            #pragma unroll
            for (int h2 = 0; h2 < 2; h2++) {
                int s = l + h2 * 32;
                float a = PN[s*4] + PN[s*4+1] + PN[s*4+2] + PN[s*4+3];
                float nrm = fmaxf(sqrtf(a), 1e-12f);
                __nv_bfloat16 hh = __float2bfloat16(nrm);
                XH[s * LDX + 128] = hh;
                NLm[s * 8] = __float2bfloat16(nrm - __bfloat162float(hh));
            }
        }

        // ---- GEMM1 single-term: warp = m16 stripe x 32 clusters (K-half) ----
        float lacc[4][4];
        #pragma unroll
        for (int j = 0; j < 4; j++)
            #pragma unroll
            for (int p = 0; p < 4; p++) lacc[j][p] = 0.0f;
        {
            uint32_t aoffA = (uint32_t)(((m0g1 + (l & 15)) * LDX + ((l >> 4) << 3)) * 2);
            uint32_t boffB = (uint32_t)(((((l >> 4) << 3) + (l & 7) + kh * 32) * LDW
                                        + (((l >> 3) & 1) << 3)) * 2);
            #pragma unroll 1
            for (int kc = 0; kc < 8; kc++) {
                uint32_t axh[4];
                ldsm4(axh, XHu + aoffA + kc * 32);
                #pragma unroll
                for (int j = 0; j < 2; j++) {
                    uint32_t bwh[4];
                    ldsm4(bwh, WHu + boffB + kc * 32 + j * 16 * LDW * 2);
                    mma_bf16(lacc[2*j],   axh, bwh[0], bwh[1]);
                    mma_bf16(lacc[2*j+1], axh, bwh[2], bwh[3]);
                }
            }
        }

        // ---- post-scale + softmax (no max-shift; logits bounded) ----
        {
            const int r0 = m0g1 + (l >> 2);
            float s40 = PN[r0*4] + PN[r0*4+1] + PN[r0*4+2] + PN[r0*4+3];
            float s41 = PN[(r0+8)*4] + PN[(r0+8)*4+1]
                      + PN[(r0+8)*4+2] + PN[(r0+8)*4+3];
            float sc0 = 1.0f / fmaxf(sqrtf(s40), 1e-12f);
            float sc1 = 1.0f / fmaxf(sqrtf(s41), 1e-12f);

            float se0 = 0.0f, se1 = 0.0f;
            #pragma unroll
            for (int j = 0; j < 4; j++) {
                float e;
                e = __expf(fmaf(lacc[j][0], sc0, bias_r[j][0])); lacc[j][0] = e; se0 += e;
                e = __expf(fmaf(lacc[j][1], sc0, bias_r[j][1])); lacc[j][1] = e; se0 += e;
                e = __expf(fmaf(lacc[j][2], sc1, bias_r[j][0])); lacc[j][2] = e; se1 += e;
                e = __expf(fmaf(lacc[j][3], sc1, bias_r[j][1])); lacc[j][3] = e; se1 += e;
            }
            se0 += __shfl_xor_sync(0xffffffffu, se0, 1);
            se0 += __shfl_xor_sync(0xffffffffu, se0, 2);
            se1 += __shfl_xor_sync(0xffffffffu, se1, 1);
            se1 += __shfl_xor_sync(0xffffffffu, se1, 2);
            if ((l & 3) == 0) {
                PS[r0 * 2 + kh]       = se0;
                PS[(r0 + 8) * 2 + kh] = se1;
            }
            // pairwise exchange between warps (w) and (w+4) only
            asm volatile("bar.sync %0, 64;" :: "r"((w & 3) + 1) : "memory");

            float inv0 = sc0 / (PS[r0 * 2] + PS[r0 * 2 + 1]);
            float inv1 = sc1 / (PS[(r0 + 8) * 2] + PS[(r0 + 8) * 2 + 1]);

            // soft stored [s][k] hi-only: conflict-free bf16x2 stores
            #pragma unroll
            for (int j = 0; j < 4; j++) {
                int k0 = kh * 32 + j * 8 + cst;
                *(uint32_t*)&SHm[r0 * LDK + k0] =
                    bf2_pack(lacc[j][0] * inv0, lacc[j][1] * inv0);
                *(uint32_t*)&SHm[(r0 + 8) * LDK + k0] =
                    bf2_pack(lacc[j][2] * inv1, lacc[j][3] * inv1);
            }
        }
        __syncthreads();                         // S2: soft + norm col ready

        // ---- GEMM2 single-term: A = soft^T (ldsm4t), B = x hi (ldsm2t) ----
        #pragma unroll 1
        for (int ks = 0; ks < 4; ks++) {
            int sb = ks * 16;
            uint32_t aoff = (uint32_t)(((sb + (l & 15)) * LDK + m0b
                                       + ((l >> 4) << 3)) * 2);
            uint32_t th[4], ash[4];
            ldsm4t(th, SHu + aoff);
            ash[0] = th[0]; ash[1] = th[2]; ash[2] = th[1]; ash[3] = th[3];
            uint32_t boff = (uint32_t)(((sb + (l & 15)) * LDX) * 2);
            #pragma unroll
            for (int j = 0; j < 8; j++) {
                int n0 = nb + j * 8;
                uint32_t bxh0, bxh1;
                ldsm2t(bxh0, bxh1, XHu + boff + n0 * 2);
                mma_bf16(vacc[j], ash, bxh0, bxh1);
            }
            if (nb == 64) {   // norm column -> a_sum (2-term: hi + lo)
                uint32_t nh0, nh1, nl0, nl1;
                ldsm2t(nh0, nh1, XHu + boff + 128 * 2);
                ldsm2t(nl0, nl1, NLu + (uint32_t)((sb + (l & 15)) * 16));
                mma_bf16(vacc8, ash, nh0, nh1);
                mma_bf16(vacc8, ash, nl0, nl1);
            }
        }
    }

    // ---- write per-block partial (no atomics) ----
    float* vdst = g_part + (size_t)blockIdx.x * PSTRIDE;
    {
        int r0 = m0b + (l >> 2);
        #pragma unroll
        for (int j = 0; j < 8; j++) {
            int c = nb + j * 8 + cst;
            vdst[r0 * C_ + c]           = vacc[j][0];
            vdst[r0 * C_ + c + 1]       = vacc[j][1];
            vdst[(r0 + 8) * C_ + c]     = vacc[j][2];
            vdst[(r0 + 8) * C_ + c + 1] = vacc[j][3];
        }
        if (nb == 64 && (l & 3) == 0) {
            vdst[8192 + r0]     = vacc8[0];
            vdst[8192 + r0 + 8] = vacc8[2];
        }
    }
}

// ---------------------------------------------------------------------------
// Wide parallel reduction: 256 partials -> 16.
#define REDV (PSTRIDE / 4)            // 2064 float4 per n
__global__ __launch_bounds__(256)
void nv_reduce_kernel() {
    int idx = blockIdx.x * 256 + threadIdx.x;
    if (idx >= N_ * REDV) return;
    int n  = idx / REDV;
    int e4 = idx - n * REDV;
    const float4* pb = (const float4*)(g_part + (size_t)n * SGROUPS * PSTRIDE)
                       + e4;
    float4 s = make_float4(0.f, 0.f, 0.f, 0.f);
    #pragma unroll 8
    for (int p = 0; p < SGROUPS; p++) {
        float4 v = pb[(size_t)p * (PSTRIDE / 4)];
        s.x += v.x; s.y += v.y; s.z += v.z; s.w += v.w;
    }
    ((float4*)(g_red + (size_t)n * PSTRIDE))[e4] = s;
}

// ---------------------------------------------------------------------------
__global__ __launch_bounds__(256)
void nv_finalize_kernel(const float* __restrict__ centroids,
                        float* __restrict__ out) {
    __shared__ float vsh[K_ * C_];
    __shared__ float ash[K_];
    __shared__ float wsum[8];

    const int n   = blockIdx.x;
    const int tid = threadIdx.x;
    const float* rb = g_red + (size_t)n * PSTRIDE;

    for (int e = tid * 4; e < K_ * C_; e += 256 * 4)
        *(float4*)&vsh[e] = *(const float4*)&rb[e];
    if (tid < K_) ash[tid] = rb[8192 + tid];
    __syncthreads();

    const int k  = tid >> 2;
    const int cb = (tid & 3) * 32;
    const float ak = ash[k];

    float ssk = 0.0f;
    #pragma unroll 8
    for (int c = 0; c < 32; c++) {
        int idx = k * C_ + cb + c;
        float v = vsh[idx] - ak * centroids[idx];
        vsh[idx] = v;
        ssk = fmaf(v, v, ssk);
    }
    ssk += __shfl_xor_sync(0xffffffffu, ssk, 1);
    ssk += __shfl_xor_sync(0xffffffffu, ssk, 2);
    float rinv = 1.0f / fmaxf(sqrtf(ssk), 1e-12f);

    float tot = 0.0f;
    #pragma unroll 8
    for (int c = 0; c < 32; c++) {
        int idx = k * C_ + cb + c;
        float tv = vsh[idx] * rinv;
        vsh[idx] = tv;
        tot = fmaf(tv, tv, tot);
    }
    #pragma unroll
    for (int off = 16; off > 0; off >>= 1)
        tot += __shfl_xor_sync(0xffffffffu, tot, off);
    if ((tid & 31) == 0) wsum[tid >> 5] = tot;
    __syncthreads();
    float total = 0.0f;
    #pragma unroll
    for (int i = 0; i < 8; i++) total += wsum[i];
    float ginv = 1.0f / fmaxf(sqrtf(total), 1e-12f);

    float* od = out + (size_t)n * K_ * C_;
    for (int i = tid; i < K_ * C_; i += 256)
        od[i] = vsh[i] * ginv;
}

// ---------------------------------------------------------------------------
extern "C" void kernel_launch(void* const* d_in, const int* in_sizes, int n_in,
                              void* d_out, int out_size) {
    const float* x         = (const float*)d_in[0];
    const float* fc_w      = (const float*)d_in[1];
    const float* fc_b      = (const float*)d_in[2];
    const float* centroids = (const float*)d_in[3];
    float* out = (float*)d_out;

    cudaFuncSetAttribute(nv_main_kernel,
                         cudaFuncAttributeMaxDynamicSharedMemorySize,
                         SMEM_TOT);

    nv_main_kernel<<<NBLK, NTH, SMEM_TOT>>>(x, fc_w, fc_b);
    nv_reduce_kernel<<<(N_ * REDV + 255) / 256, 256>>>();
    nv_finalize_kernel<<<N_, 256>>>(centroids, out);
}

// round 17
// speedup vs baseline: 1.5212x; 1.0212x over previous
#include <cuda_runtime.h>
#include <cuda_bf16.h>
#include <math.h>
#include <stdint.h>

#define N_  16
#define C_  128
#define S_  16384
#define K_  64
#define TS  64
#define TILES 16
#define SGROUPS (S_ / (TS * TILES))   // 16
#define NBLK (N_ * SGROUPS)           // 256
#define NTH 256
#define LDX 136   // bf16 row stride x tiles [s][c] (col 128 = ||x|| hi)
#define LDW 136
#define LDK 72    // bf16 row stride soft [s][k]
#define LDR 68    // f32 row stride RAW staging [c][s]
#define PSTRIDE 8256                  // 8192 vacc + 64 asum per block partial

__device__ float g_part[NBLK * PSTRIDE];
__device__ float g_red[N_ * PSTRIDE];

// ---------------------------------------------------------------------------
__device__ __forceinline__ uint32_t s2u(const void* p) {
    uint32_t a;
    asm("{ .reg .u64 t; cvta.to.shared.u64 t, %1; cvt.u32.u64 %0, t; }"
        : "=r"(a) : "l"(p));
    return a;
}
__device__ __forceinline__ void ldsm4(uint32_t* r, uint32_t addr) {
    asm volatile("ldmatrix.sync.aligned.m8n8.x4.shared.b16 {%0,%1,%2,%3}, [%4];"
                 : "=r"(r[0]), "=r"(r[1]), "=r"(r[2]), "=r"(r[3]) : "r"(addr));
}
__device__ __forceinline__ void ldsm4t(uint32_t* r, uint32_t addr) {
    asm volatile("ldmatrix.sync.aligned.m8n8.x4.trans.shared.b16 {%0,%1,%2,%3}, [%4];"
                 : "=r"(r[0]), "=r"(r[1]), "=r"(r[2]), "=r"(r[3]) : "r"(addr));
}
__device__ __forceinline__ void ldsm2t(uint32_t& r0, uint32_t& r1, uint32_t addr) {
    asm volatile("ldmatrix.sync.aligned.m8n8.x2.trans.shared.b16 {%0,%1}, [%2];"
                 : "=r"(r0), "=r"(r1) : "r"(addr));
}
__device__ __forceinline__ void mma_bf16(float* d, const uint32_t* a,
                                         uint32_t b0, uint32_t b1) {
    asm volatile("mma.sync.aligned.m16n8k16.row.col.f32.bf16.bf16.f32 "
                 "{%0,%1,%2,%3}, {%4,%5,%6,%7}, {%8,%9}, {%0,%1,%2,%3};"
                 : "+f"(d[0]), "+f"(d[1]), "+f"(d[2]), "+f"(d[3])
                 : "r"(a[0]), "r"(a[1]), "r"(a[2]), "r"(a[3]), "r"(b0), "r"(b1));
}
__device__ __forceinline__ uint32_t bf2_pack(float lo, float hi) {
    __nv_bfloat162 p;
    p.x = __float2bfloat16(lo); p.y = __float2bfloat16(hi);
    return *(uint32_t*)&p;
}
__device__ __forceinline__ void cp16(uint32_t dst, const float* src) {
    asm volatile("cp.async.ca.shared.global [%0], [%1], 16;"
                 :: "r"(dst), "l"(__cvta_generic_to_global(src)));
}
__device__ __forceinline__ void cp_commit() {
    asm volatile("cp.async.commit_group;");
}
__device__ __forceinline__ void cp_wait0() {
    asm volatile("cp.async.wait_group 0;" ::: "memory");
}

// ---------------------------------------------------------------------------
// smem byte offsets (ldsm bases 128-aligned)
#define OFF_XH   0            // 64 x 136 bf16 = 17408
#define OFF_WH   17408        // 64 x 136 bf16 = 17408
#define OFF_SH   34816        // soft hi [s][k] 64 x 72 bf16 = 9216
#define OFF_NL   44032        // norm-lo [64][8] bf16 = 1024
#define OFF_BB   45056        // 64 f32
#define OFF_PN   45312        // float[64][4]
#define OFF_PS   46336        // float[64][2]
#define OFF_RAW  46848        // f32 [128][68] = 34816
#define SMEM_TOT 81664

__global__ __launch_bounds__(NTH, 2)
void nv_main_kernel(const float* __restrict__ x,
                    const float* __restrict__ fc_w,
                    const float* __restrict__ fc_b) {
    extern __shared__ char smem[];
    __nv_bfloat16* XH  = (__nv_bfloat16*)(smem + OFF_XH);
    __nv_bfloat16* WH  = (__nv_bfloat16*)(smem + OFF_WH);
    __nv_bfloat16* SHm = (__nv_bfloat16*)(smem + OFF_SH);
    __nv_bfloat16* NLm = (__nv_bfloat16*)(smem + OFF_NL);
    float* BB  = (float*)(smem + OFF_BB);
    float* PN  = (float*)(smem + OFF_PN);
    float* PS  = (float*)(smem + OFF_PS);
    float* RAW = (float*)(smem + OFF_RAW);

    const uint32_t XHu = s2u(XH), WHu = s2u(WH);
    const uint32_t SHu = s2u(SHm), NLu = s2u(NLm);
    const uint32_t RAWu = s2u(RAW);

    const int n   = blockIdx.x >> 4;
    const int g   = blockIdx.x & (SGROUPS - 1);
    const int tid = threadIdx.x;
    const int l   = tid & 31;
    const int w   = tid >> 5;            // 0..7
    const int sl  = tid & 63;            // position (convert)
    const int q   = tid >> 6;            // channel quarter 0..3

    const int m0g1 = (w & 3) * 16;
    const int kh   = w >> 2;
    const int m0b  = (w & 3) * 16;
    const int nb   = (w >> 2) * 64;

    const float* xbase = x + (size_t)n * C_ * S_;
    const int sbase = g * (TS * TILES);

    // chunk mapping for cp.async: 2048 16B chunks, 8 per thread
    const int cp_row0 = tid >> 4;          // +16 per round
    const int cp_col  = (tid & 15) * 4;    // float offset within row

    // ---- prefetch tile 0 ----
    #pragma unroll
    for (int r = 0; r < 8; r++) {
        int row = cp_row0 + r * 16;
        cp16(RAWu + (uint32_t)((row * LDR + cp_col) * 4),
             xbase + (size_t)row * S_ + sbase + cp_col);
    }
    cp_commit();

    // ---- load fc_w hi + bias (once per block) ----
    for (int i = tid; i < K_ * C_; i += NTH) {
        int k = i >> 7, c = i & 127;
        WH[k * LDW + c] = __float2bfloat16(fc_w[i]);
    }
    if (tid < K_) BB[tid] = fc_b[tid];
    __syncthreads();

    const int cst = (l & 3) * 2;
    float bias_r[4][2];
    #pragma unroll
    for (int j = 0; j < 4; j++) {
        bias_r[j][0] = BB[kh * 32 + j * 8 + cst];
        bias_r[j][1] = BB[kh * 32 + j * 8 + cst + 1];
    }

    float vacc[8][4];
    #pragma unroll
    for (int j = 0; j < 8; j++)
        #pragma unroll
        for (int p = 0; p < 4; p++) vacc[j][p] = 0.0f;
    float vacc8[4] = {0.f, 0.f, 0.f, 0.f};   // norm-column (a_sum)

    #pragma unroll 1
    for (int t = 0; t < TILES; t++) {
        cp_wait0();                              // tile t staged (per-thread)
        __syncthreads();                         // A: visibility + prev consumers

        // ---- convert from RAW (LDS, conflict-free): hi-only bf16 + ss ----
        float ss = 0.0f;
        #pragma unroll
        for (int ch = 0; ch < 4; ch++) {
            const int c0 = q * 32 + ch * 8;
            uint32_t hp[4];
            #pragma unroll
            for (int u = 0; u < 4; u++) {
                float v0 = RAW[(c0 + 2*u)     * LDR + sl];
                float v1 = RAW[(c0 + 2*u + 1) * LDR + sl];
                ss = fmaf(v0, v0, ss); ss = fmaf(v1, v1, ss);
                hp[u] = bf2_pack(v0, v1);
            }
            *(uint4*)&XH[sl * LDX + c0] = make_uint4(hp[0], hp[1], hp[2], hp[3]);
        }
        PN[sl * 4 + q] = ss;
        __syncthreads();                         // S1: XH + PN ready, RAW free

        // ---- prefetch tile t+1 into RAW ----
        if (t + 1 < TILES) {
            const int s1 = sbase + (t + 1) * TS;
            #pragma unroll
            for (int r = 0; r < 8; r++) {
                int row = cp_row0 + r * 16;
                cp16(RAWu + (uint32_t)((row * LDR + cp_col) * 4),
                     xbase + (size_t)row * S_ + s1 + cp_col);
            }
            cp_commit();
        }

        // norm column (c=128): ||x_s|| hi in XH, lo in NL (warp 0)
        if (tid < 32) {
            #pragma unroll
            for (int h2 = 0; h2 < 2; h2++) {
                int s = l + h2 * 32;
                float a = PN[s*4] + PN[s*4+1] + PN[s*4+2] + PN[s*4+3];
                float nrm = fmaxf(sqrtf(a), 1e-12f);
                __nv_bfloat16 hh = __float2bfloat16(nrm);
                XH[s * LDX + 128] = hh;
                NLm[s * 8] = __float2bfloat16(nrm - __bfloat162float(hh));
            }
        }

        // ---- GEMM1 single-term: warp = m16 stripe x 32 clusters (K-half) ----
        float lacc[4][4];
        #pragma unroll
        for (int j = 0; j < 4; j++)
            #pragma unroll
            for (int p = 0; p < 4; p++) lacc[j][p] = 0.0f;
        {
            uint32_t aoffA = (uint32_t)(((m0g1 + (l & 15)) * LDX + ((l >> 4) << 3)) * 2);
            uint32_t boffB = (uint32_t)(((((l >> 4) << 3) + (l & 7) + kh * 32) * LDW
                                        + (((l >> 3) & 1) << 3)) * 2);
            #pragma unroll 1
            for (int kc = 0; kc < 8; kc++) {
                uint32_t axh[4];
                ldsm4(axh, XHu + aoffA + kc * 32);
                #pragma unroll
                for (int j = 0; j < 2; j++) {
                    uint32_t bwh[4];
                    ldsm4(bwh, WHu + boffB + kc * 32 + j * 16 * LDW * 2);
                    mma_bf16(lacc[2*j],   axh, bwh[0], bwh[1]);
                    mma_bf16(lacc[2*j+1], axh, bwh[2], bwh[3]);
                }
            }
        }

        // ---- post-scale + softmax (no max-shift; logits bounded) ----
        {
            const int r0 = m0g1 + (l >> 2);
            float s40 = PN[r0*4] + PN[r0*4+1] + PN[r0*4+2] + PN[r0*4+3];
            float s41 = PN[(r0+8)*4] + PN[(r0+8)*4+1]
                      + PN[(r0+8)*4+2] + PN[(r0+8)*4+3];
            float sc0 = 1.0f / fmaxf(sqrtf(s40), 1e-12f);
            float sc1 = 1.0f / fmaxf(sqrtf(s41), 1e-12f);

            float se0 = 0.0f, se1 = 0.0f;
            #pragma unroll
            for (int j = 0; j < 4; j++) {
                float e;
                e = __expf(fmaf(lacc[j][0], sc0, bias_r[j][0])); lacc[j][0] = e; se0 += e;
                e = __expf(fmaf(lacc[j][1], sc0, bias_r[j][1])); lacc[j][1] = e; se0 += e;
                e = __expf(fmaf(lacc[j][2], sc1, bias_r[j][0])); lacc[j][2] = e; se1 += e;
                e = __expf(fmaf(lacc[j][3], sc1, bias_r[j][1])); lacc[j][3] = e; se1 += e;
            }
            se0 += __shfl_xor_sync(0xffffffffu, se0, 1);
            se0 += __shfl_xor_sync(0xffffffffu, se0, 2);
            se1 += __shfl_xor_sync(0xffffffffu, se1, 1);
            se1 += __shfl_xor_sync(0xffffffffu, se1, 2);
            if ((l & 3) == 0) {
                PS[r0 * 2 + kh]       = se0;
                PS[(r0 + 8) * 2 + kh] = se1;
            }
            // pairwise exchange between warps (w) and (w+4) only
            asm volatile("bar.sync %0, 64;" :: "r"((w & 3) + 1) : "memory");

            float inv0 = sc0 / (PS[r0 * 2] + PS[r0 * 2 + 1]);
            float inv1 = sc1 / (PS[(r0 + 8) * 2] + PS[(r0 + 8) * 2 + 1]);

            #pragma unroll
            for (int j = 0; j < 4; j++) {
                int k0 = kh * 32 + j * 8 + cst;
                *(uint32_t*)&SHm[r0 * LDK + k0] =
                    bf2_pack(lacc[j][0] * inv0, lacc[j][1] * inv0);
                *(uint32_t*)&SHm[(r0 + 8) * LDK + k0] =
                    bf2_pack(lacc[j][2] * inv1, lacc[j][3] * inv1);
            }
        }
        __syncthreads();                         // S2: soft + norm col ready

        // ---- GEMM2 single-term: A = soft^T (ldsm4t), B = x hi (ldsm4t) ----
        #pragma unroll 1
        for (int ks = 0; ks < 4; ks++) {
            int sb = ks * 16;
            uint32_t aoff = (uint32_t)(((sb + (l & 15)) * LDK + m0b
                                       + ((l >> 4) << 3)) * 2);
            uint32_t th[4], ash[4];
            ldsm4t(th, SHu + aoff);
            ash[0] = th[0]; ash[1] = th[2]; ash[2] = th[1]; ash[3] = th[3];
            #pragma unroll
            for (int half = 0; half < 4; half++) {
                int n0 = nb + half * 16;
                uint32_t boff = (uint32_t)(((sb + (l & 15)) * LDX + n0
                                           + ((l >> 4) << 3)) * 2);
                uint32_t bxh[4];
                ldsm4t(bxh, XHu + boff);
                mma_bf16(vacc[2*half],     ash, bxh[0], bxh[1]);
                mma_bf16(vacc[2*half + 1], ash, bxh[2], bxh[3]);
            }
            if (nb == 64) {   // norm column -> a_sum (2-term: hi + lo)
                uint32_t boffN = (uint32_t)(((sb + (l & 15)) * LDX) * 2);
                uint32_t nh0, nh1, nl0, nl1;
                ldsm2t(nh0, nh1, XHu + boffN + 128 * 2);
                ldsm2t(nl0, nl1, NLu + (uint32_t)((sb + (l & 15)) * 16));
                mma_bf16(vacc8, ash, nh0, nh1);
                mma_bf16(vacc8, ash, nl0, nl1);
            }
        }
    }

    // ---- write per-block partial (no atomics, float2) ----
    float* vdst = g_part + (size_t)blockIdx.x * PSTRIDE;
    {
        int r0 = m0b + (l >> 2);
        #pragma unroll
        for (int j = 0; j < 8; j++) {
            int c = nb + j * 8 + cst;
            *(float2*)&vdst[r0 * C_ + c]       = make_float2(vacc[j][0], vacc[j][1]);
            *(float2*)&vdst[(r0 + 8) * C_ + c] = make_float2(vacc[j][2], vacc[j][3]);
        }
        if (nb == 64 && (l & 3) == 0) {
            vdst[8192 + r0]     = vacc8[0];
            vdst[8192 + r0 + 8] = vacc8[2];
        }
    }
}

// ---------------------------------------------------------------------------
// Wide parallel reduction: 256 partials -> 16.
#define REDV (PSTRIDE / 4)            // 2064 float4 per n
__global__ __launch_bounds__(256)
void nv_reduce_kernel() {
    int idx = blockIdx.x * 256 + threadIdx.x;
    if (idx >= N_ * REDV) return;
    int n  = idx / REDV;
    int e4 = idx - n * REDV;
    const float4* pb = (const float4*)(g_part + (size_t)n * SGROUPS * PSTRIDE)
                       + e4;
    float4 s = make_float4(0.f, 0.f, 0.f, 0.f);
    #pragma unroll 8
    for (int p = 0; p < SGROUPS; p++) {
        float4 v = pb[(size_t)p * (PSTRIDE / 4)];
        s.x += v.x; s.y += v.y; s.z += v.z; s.w += v.w;
    }
    ((float4*)(g_red + (size_t)n * PSTRIDE))[e4] = s;
}

// ---------------------------------------------------------------------------
__global__ __launch_bounds__(256)
void nv_finalize_kernel(const float* __restrict__ centroids,
                        float* __restrict__ out) {
    __shared__ float vsh[K_ * C_];
    __shared__ float ash[K_];
    __shared__ float wsum[8];

    const int n   = blockIdx.x;
    const int tid = threadIdx.x;
    const float* rb = g_red + (size_t)n * PSTRIDE;

    for (int e = tid * 4; e < K_ * C_; e += 256 * 4)
        *(float4*)&vsh[e] = *(const float4*)&rb[e];
    if (tid < K_) ash[tid] = rb[8192 + tid];
    __syncthreads();

    const int k  = tid >> 2;
    const int cb = (tid & 3) * 32;
    const float ak = ash[k];

    float ssk = 0.0f;
    #pragma unroll 8
    for (int c = 0; c < 32; c++) {
        int idx = k * C_ + cb + c;
        float v = vsh[idx] - ak * centroids[idx];
        vsh[idx] = v;
        ssk = fmaf(v, v, ssk);
    }
    ssk += __shfl_xor_sync(0xffffffffu, ssk, 1);
    ssk += __shfl_xor_sync(0xffffffffu, ssk, 2);
    float rinv = 1.0f / fmaxf(sqrtf(ssk), 1e-12f);

    float tot = 0.0f;
    #pragma unroll 8
    for (int c = 0; c < 32; c++) {
        int idx = k * C_ + cb + c;
        float tv = vsh[idx] * rinv;
        vsh[idx] = tv;
        tot = fmaf(tv, tv, tot);
    }
    #pragma unroll
    for (int off = 16; off > 0; off >>= 1)
        tot += __shfl_xor_sync(0xffffffffu, tot, off);
    if ((tid & 31) == 0) wsum[tid >> 5] = tot;
    __syncthreads();
    float total = 0.0f;
    #pragma unroll
    for (int i = 0; i < 8; i++) total += wsum[i];
    float ginv = 1.0f / fmaxf(sqrtf(total), 1e-12f);

    float* od = out + (size_t)n * K_ * C_;
    for (int i = tid; i < K_ * C_; i += 256)
        od[i] = vsh[i] * ginv;
}

// ---------------------------------------------------------------------------
extern "C" void kernel_launch(void* const* d_in, const int* in_sizes, int n_in,
                              void* d_out, int out_size) {
    const float* x         = (const float*)d_in[0];
    const float* fc_w      = (const float*)d_in[1];
    const float* fc_b      = (const float*)d_in[2];
    const float* centroids = (const float*)d_in[3];
    float* out = (float*)d_out;

    cudaFuncSetAttribute(nv_main_kernel,
                         cudaFuncAttributeMaxDynamicSharedMemorySize,
                         SMEM_TOT);

    nv_main_kernel<<<NBLK, NTH, SMEM_TOT>>>(x, fc_w, fc_b);
    nv_reduce_kernel<<<(N_ * REDV + 255) / 256, 256>>>();
    nv_finalize_kernel<<<N_, 256>>>(centroids, out);
}